// round 4
// baseline (speedup 1.0000x reference)
#include <cuda_runtime.h>

// Chunk-local reverse inclusive cumsum with scale fusion.
//   g: [B, T, H] f32, BT=64 chunks along T, H=64.
//   out[b, c, t, h] = SCALE * sum_{s >= t} g[b, c, s, h]
//
// Mapping: ONE THREAD PER (chunk, head) scalar column. 262144 threads
// (~55 warps/SM) to cover memory latency; loads batched UNROLL=16 deep
// into 16 scalar registers — cheap enough that ptxas actually keeps the
// whole batch in flight (float2/float4 variants collapsed to MLP~4).
// Per warp each load touches 128 contiguous bytes: fully coalesced.
// Pure streaming: read once, write once.

static constexpr int BT = 64;
static constexpr int H  = 64;
static constexpr int UNROLL = 16;
static constexpr float SCALE = 0.5f;

__global__ __launch_bounds__(256)
void rev_cumsum_kernel(const float* __restrict__ g,
                       float* __restrict__ out,
                       int n_cols)  // total (chunk, head) columns
{
    int tid = blockIdx.x * blockDim.x + threadIdx.x;
    if (tid >= n_cols) return;

    int h     = tid & (H - 1);            // 0..63
    int chunk = tid >> 6;                 // global chunk index

    size_t base = (size_t)chunk * (BT * H) + h;
    const float* __restrict__ gp = g   + base;
    float*       __restrict__ op = out + base;

    float run = 0.f;

    #pragma unroll
    for (int grp = BT / UNROLL - 1; grp >= 0; --grp) {
        // Batch-issue UNROLL independent 32-bit loads (front-batched MLP).
        float v[UNROLL];
        #pragma unroll
        for (int j = 0; j < UNROLL; ++j)
            v[j] = gp[(grp * UNROLL + j) * H];

        // Serial suffix-sum over the register batch; stores fire-and-forget.
        #pragma unroll
        for (int j = UNROLL - 1; j >= 0; --j) {
            run += v[j];
            op[(grp * UNROLL + j) * H] = run * SCALE;
        }
    }
}

extern "C" void kernel_launch(void* const* d_in, const int* in_sizes, int n_in,
                              void* d_out, int out_size)
{
    const float* g   = (const float*)d_in[0];
    float*       out = (float*)d_out;

    int total_elems = in_sizes[0];           // B * T * H
    int n_cols = total_elems / BT;           // chunks * H columns

    int threads = 256;
    int blocks  = (n_cols + threads - 1) / threads;
    rev_cumsum_kernel<<<blocks, threads>>>(g, out, n_cols);
}

// round 5
// speedup vs baseline: 1.0013x; 1.0013x over previous
#include <cuda_runtime.h>

// Chunk-local reverse inclusive cumsum with scale fusion.
//   g: [B, T, H] f32, BT=64 chunks along T, H=64.
//   out[b, c, t, h] = SCALE * sum_{s >= t} g[b, c, s, h]
//
// Mapping: each (chunk, quad-column) is split across 8 threads (8 rows each,
// float4 width). 524288 threads total -> high occupancy AND 128-bit memory
// ops (low LSU issue cost). Each thread loads its 8 float4s (all must stay
// live for the segment total -> guaranteed MLP=8), the 8 segment totals are
// suffix-scanned across lanes with shuffles, then outputs are stored with
// STG.128. Read once, write once, no smem, no block sync.
//
// Warp layout: lane = seg*4 + c, where c = quad-within-group (4 adjacent
// float4 columns) and seg = t-segment (0..7). One warp covers 4 quad-columns
// x the whole chunk; 4 warps per chunk.

static constexpr int BT = 64;
static constexpr int H  = 64;
static constexpr int HQ = H / 4;          // 16 float4 columns per row
static constexpr int SEGS = 8;            // t-segments per chunk
static constexpr int RPS  = BT / SEGS;    // rows per segment = 8
static constexpr float SCALE = 0.5f;

__global__ __launch_bounds__(256)
void rev_cumsum_kernel(const float4* __restrict__ g,
                       float4* __restrict__ out,
                       int n_threads)
{
    int tid = blockIdx.x * blockDim.x + threadIdx.x;
    if (tid >= n_threads) return;

    int c     = tid & 3;                  // quad within group of 4
    int seg   = (tid >> 2) & (SEGS - 1);  // t-segment 0..7
    int wq    = (tid >> 5) & 3;           // quad-group 0..3
    int chunk = tid >> 7;                 // global chunk index

    size_t base = (size_t)chunk * (BT * HQ) + (size_t)(wq * 4 + c);
    const float4* __restrict__ gp = g   + base;
    float4*       __restrict__ op = out + base;

    int row0 = seg * RPS;

    // Load the whole segment: 8 independent LDG.128, all live until totals.
    float4 v[RPS];
    #pragma unroll
    for (int j = 0; j < RPS; ++j)
        v[j] = gp[(row0 + j) * HQ];

    // Segment totals.
    float tx = 0.f, ty = 0.f, tz = 0.f, tw = 0.f;
    #pragma unroll
    for (int j = 0; j < RPS; ++j) {
        tx += v[j].x; ty += v[j].y; tz += v[j].z; tw += v[j].w;
    }

    // Exclusive suffix-scan of totals across segments (same c, lane stride 4).
    // Step 1: shift down by one segment (seg 7 gets 0).
    float cx = __shfl_down_sync(0xffffffffu, tx, 4);
    float cy = __shfl_down_sync(0xffffffffu, ty, 4);
    float cz = __shfl_down_sync(0xffffffffu, tz, 4);
    float cw = __shfl_down_sync(0xffffffffu, tw, 4);
    if (seg == SEGS - 1) { cx = 0.f; cy = 0.f; cz = 0.f; cw = 0.f; }
    // Inclusive suffix-scan of the shifted values: 3 Hillis-Steele steps.
    #pragma unroll
    for (int d = 1; d < SEGS; d <<= 1) {
        float ax = __shfl_down_sync(0xffffffffu, cx, 4 * d);
        float ay = __shfl_down_sync(0xffffffffu, cy, 4 * d);
        float az = __shfl_down_sync(0xffffffffu, cz, 4 * d);
        float aw = __shfl_down_sync(0xffffffffu, cw, 4 * d);
        if (seg + d < SEGS) { cx += ax; cy += ay; cz += az; cw += aw; }
    }
    // cx.. = sum of totals of all segments strictly after this one.

    // Reverse inclusive cumsum within the segment, seeded with the carry.
    float rx = cx, ry = cy, rz = cz, rw = cw;
    #pragma unroll
    for (int j = RPS - 1; j >= 0; --j) {
        rx += v[j].x; ry += v[j].y; rz += v[j].z; rw += v[j].w;
        float4 o;
        o.x = rx * SCALE; o.y = ry * SCALE; o.z = rz * SCALE; o.w = rw * SCALE;
        op[(row0 + j) * HQ] = o;
    }
}

extern "C" void kernel_launch(void* const* d_in, const int* in_sizes, int n_in,
                              void* d_out, int out_size)
{
    const float4* g   = (const float4*)d_in[0];
    float4*       out = (float4*)d_out;

    int total_elems = in_sizes[0];                 // B * T * H
    int chunks    = total_elems / (BT * H);        // 4096
    int n_threads = chunks * (SEGS * HQ);          // 8 segs * 16 quads = 128/chunk

    int threads = 256;
    int blocks  = (n_threads + threads - 1) / threads;
    rev_cumsum_kernel<<<blocks, threads>>>(g, out, n_threads);
}

// round 6
// speedup vs baseline: 1.0132x; 1.0119x over previous
#include <cuda_runtime.h>

// Chunk-local reverse inclusive cumsum with scale fusion.
//   g: [B, T, H] f32, BT=64 chunks along T, H=64.
//   out[b, c, t, h] = SCALE * sum_{s >= t} g[b, c, s, h]
//
// R6: R5 structure (8 threads per (chunk, quad-column), guaranteed MLP=8,
// warp-shuffle suffix-scan of segment totals, STG.128 outputs) + streaming
// cache hints (__ldcs / __stcs, evict-first) to minimize L2 churn between
// the read and write streams. Kernel is at the measured ~7 TB/s LTS
// roofline (134.2 MB compulsory traffic); this round tests whether cache
// policy buys the last few percent.

static constexpr int BT = 64;
static constexpr int H  = 64;
static constexpr int HQ = H / 4;          // 16 float4 columns per row
static constexpr int SEGS = 8;            // t-segments per chunk
static constexpr int RPS  = BT / SEGS;    // rows per segment = 8
static constexpr float SCALE = 0.5f;

__global__ __launch_bounds__(256)
void rev_cumsum_kernel(const float4* __restrict__ g,
                       float4* __restrict__ out,
                       int n_threads)
{
    int tid = blockIdx.x * blockDim.x + threadIdx.x;
    if (tid >= n_threads) return;

    int c     = tid & 3;                  // quad within group of 4
    int seg   = (tid >> 2) & (SEGS - 1);  // t-segment 0..7
    int wq    = (tid >> 5) & 3;           // quad-group 0..3
    int chunk = tid >> 7;                 // global chunk index

    size_t base = (size_t)chunk * (BT * HQ) + (size_t)(wq * 4 + c);
    const float4* __restrict__ gp = g   + base;
    float4*       __restrict__ op = out + base;

    int row0 = seg * RPS;

    // Load the whole segment: 8 independent LDG.128.E.CS, all live until
    // the totals are computed -> guaranteed MLP=8.
    float4 v[RPS];
    #pragma unroll
    for (int j = 0; j < RPS; ++j)
        v[j] = __ldcs(&gp[(row0 + j) * HQ]);

    // Segment totals.
    float tx = 0.f, ty = 0.f, tz = 0.f, tw = 0.f;
    #pragma unroll
    for (int j = 0; j < RPS; ++j) {
        tx += v[j].x; ty += v[j].y; tz += v[j].z; tw += v[j].w;
    }

    // Exclusive suffix-scan of totals across segments (same c, lane stride 4).
    float cx = __shfl_down_sync(0xffffffffu, tx, 4);
    float cy = __shfl_down_sync(0xffffffffu, ty, 4);
    float cz = __shfl_down_sync(0xffffffffu, tz, 4);
    float cw = __shfl_down_sync(0xffffffffu, tw, 4);
    if (seg == SEGS - 1) { cx = 0.f; cy = 0.f; cz = 0.f; cw = 0.f; }
    #pragma unroll
    for (int d = 1; d < SEGS; d <<= 1) {
        float ax = __shfl_down_sync(0xffffffffu, cx, 4 * d);
        float ay = __shfl_down_sync(0xffffffffu, cy, 4 * d);
        float az = __shfl_down_sync(0xffffffffu, cz, 4 * d);
        float aw = __shfl_down_sync(0xffffffffu, cw, 4 * d);
        if (seg + d < SEGS) { cx += ax; cy += ay; cz += az; cw += aw; }
    }
    // cx.. = sum of totals of all segments strictly after this one.

    // Reverse inclusive cumsum within the segment, seeded with the carry;
    // streaming stores (evict-first).
    float rx = cx, ry = cy, rz = cz, rw = cw;
    #pragma unroll
    for (int j = RPS - 1; j >= 0; --j) {
        rx += v[j].x; ry += v[j].y; rz += v[j].z; rw += v[j].w;
        float4 o;
        o.x = rx * SCALE; o.y = ry * SCALE; o.z = rz * SCALE; o.w = rw * SCALE;
        __stcs(&op[(row0 + j) * HQ], o);
    }
}

extern "C" void kernel_launch(void* const* d_in, const int* in_sizes, int n_in,
                              void* d_out, int out_size)
{
    const float4* g   = (const float4*)d_in[0];
    float4*       out = (float4*)d_out;

    int total_elems = in_sizes[0];                 // B * T * H
    int chunks    = total_elems / (BT * H);        // 4096
    int n_threads = chunks * (SEGS * HQ);          // 128 threads per chunk

    int threads = 256;
    int blocks  = (n_threads + threads - 1) / threads;
    rev_cumsum_kernel<<<blocks, threads>>>(g, out, n_threads);
}